// round 3
// baseline (speedup 1.0000x reference)
#include <cuda_runtime.h>

#define N_NODES 50000
#define N_EDGES 800000
#define F_IN    128
#define F_HID   128
#define F_OUT   64

// ---------------- scratch (static device globals; 16B-aligned for float4/red.v4) ----------------
__device__ __align__(16) float g_agg[N_NODES * F_IN];  // layer1 agg [N,128]; reused as layer2 agg [N,64]
__device__ __align__(16) float g_h1 [N_NODES * F_HID]; // relu(layer1) * norm_out  [N,128]
__device__ __align__(16) float g_y2 [N_NODES * F_OUT]; // g_h1 @ W2                [N,64]
__device__ __align__(16) float g_norm_out[N_NODES];
__device__ __align__(16) float g_norm_in [N_NODES];
__device__ __align__(16) int   g_deg_out[N_NODES];
__device__ __align__(16) int   g_deg_in [N_NODES];

__device__ __forceinline__ int clampi(int v) {
    return v < 0 ? 0 : (v >= N_NODES ? N_NODES - 1 : v);
}

// ---------------- tiny helpers ----------------
__global__ void k_zero_f4(float4* __restrict__ p, int n4) {
    int i = blockIdx.x * blockDim.x + threadIdx.x;
    if (i < n4) p[i] = make_float4(0.f, 0.f, 0.f, 0.f);
}

__global__ void k_zero_deg() {
    int i = blockIdx.x * blockDim.x + threadIdx.x;
    if (i < N_NODES) { g_deg_out[i] = 0; g_deg_in[i] = 0; }
}

__global__ void k_deg(const int* __restrict__ src, const int* __restrict__ dst) {
    int e = blockIdx.x * blockDim.x + threadIdx.x;
    if (e < N_EDGES) {
        atomicAdd(&g_deg_out[clampi(src[e])], 1);
        atomicAdd(&g_deg_in [clampi(dst[e])], 1);
    }
}

__global__ void k_norm() {
    int i = blockIdx.x * blockDim.x + threadIdx.x;
    if (i < N_NODES) {
        g_norm_out[i] = rsqrtf((float)max(g_deg_out[i], 1));
        g_norm_in [i] = rsqrtf((float)max(g_deg_in [i], 1));
    }
}

// ---------------- edge scatter: agg[dst] += X[src] (* norm_out[src]) ----------------
// One thread per (edge, float4-chunk). F4 = feature_dim/4.
template<int F4, bool SCALE>
__global__ void k_scatter(const float* __restrict__ X,
                          const int* __restrict__ src,
                          const int* __restrict__ dst,
                          float* __restrict__ agg) {
    int idx = blockIdx.x * blockDim.x + threadIdx.x;
    if (idx >= N_EDGES * F4) return;
    int e = idx / F4;
    int q = idx - e * F4;
    int s = clampi(src[e]);
    int d = clampi(dst[e]);
    float4 v = ((const float4*)X)[(size_t)s * F4 + q];
    if (SCALE) {
        float f = g_norm_out[s];
        v.x *= f; v.y *= f; v.z *= f; v.w *= f;
    }
    float* p = agg + ((size_t)d * F4 + q) * 4;
    asm volatile("red.global.add.v4.f32 [%0], {%1,%2,%3,%4};"
                 :: "l"(p), "f"(v.x), "f"(v.y), "f"(v.z), "f"(v.w) : "memory");
}

// ---------------- tiled fp32 GEMM:  Y = f(X [*norm_in]) @ W  ----------------
// K = 128 fixed. Tile: 128 rows x NCOLS cols, 256 threads.
// LAYER1: scale rows by norm_in on load; epilogue = relu(+bias) * norm_out.
template<int NCOLS, bool LAYER1>
__global__ void k_gemm(const float* __restrict__ X, const float* __restrict__ W,
                       const float* __restrict__ bias, float* __restrict__ Y) {
    constexpr int K   = 128;
    constexpr int TM  = 128;
    constexpr int CG  = NCOLS / 8;     // column groups (8 cols each)
    constexpr int RG  = 256 / CG;      // row groups
    constexpr int RPT = TM / RG;       // rows per thread
    constexpr int XLD = 132;           // padded X row stride (floats), 16B-aligned

    extern __shared__ float sm[];
    float* sW = sm;                    // [K][NCOLS]
    float* sX = sm + K * NCOLS;        // [TM][XLD]

    int t    = threadIdx.x;
    int row0 = blockIdx.x * TM;

    // load W tile (whole W fits)
    for (int i = t; i < K * NCOLS / 4; i += 256)
        ((float4*)sW)[i] = ((const float4*)W)[i];

    // load X tile, optionally scaled by norm_in
    {
        int kq = t & 31;               // which float4 along K
        int rr = t >> 5;               // 8 rows per pass
        for (int r = rr; r < TM; r += 8) {
            int gr = row0 + r;
            float4 v = make_float4(0.f, 0.f, 0.f, 0.f);
            if (gr < N_NODES) {
                v = ((const float4*)X)[(size_t)gr * (K / 4) + kq];
                if (LAYER1) {
                    float s = g_norm_in[gr];
                    v.x *= s; v.y *= s; v.z *= s; v.w *= s;
                }
            }
            *(float4*)(sX + r * XLD + kq * 4) = v;
        }
    }
    __syncthreads();

    int cg = t % CG;
    int rg = t / CG;
    int c0 = cg * 8;

    float acc[RPT][8];
#pragma unroll
    for (int i = 0; i < RPT; i++)
#pragma unroll
        for (int j = 0; j < 8; j++) acc[i][j] = 0.f;

#pragma unroll 2
    for (int k4 = 0; k4 < K / 4; k4++) {
        float4 xv[RPT];
#pragma unroll
        for (int i = 0; i < RPT; i++)
            xv[i] = *(const float4*)(sX + (rg * RPT + i) * XLD + k4 * 4);
#pragma unroll
        for (int kk = 0; kk < 4; kk++) {
            int k = k4 * 4 + kk;
            float4 w0 = *(const float4*)(sW + k * NCOLS + c0);
            float4 w1 = *(const float4*)(sW + k * NCOLS + c0 + 4);
            float wv[8] = {w0.x, w0.y, w0.z, w0.w, w1.x, w1.y, w1.z, w1.w};
#pragma unroll
            for (int i = 0; i < RPT; i++) {
                float x = (&xv[i].x)[kk];
#pragma unroll
                for (int j = 0; j < 8; j++)
                    acc[i][j] = fmaf(x, wv[j], acc[i][j]);
            }
        }
    }

#pragma unroll
    for (int i = 0; i < RPT; i++) {
        int gr = row0 + rg * RPT + i;
        if (gr >= N_NODES) continue;
        float so = LAYER1 ? g_norm_out[gr] : 1.f;
        float res[8];
#pragma unroll
        for (int j = 0; j < 8; j++) {
            float v = acc[i][j];
            if (LAYER1) {
                v += bias[c0 + j];
                v = fmaxf(v, 0.f) * so;   // relu(z)*s == relu(z*s), s>0
            }
            res[j] = v;
        }
        float4* yp = (float4*)(Y + (size_t)gr * NCOLS + c0);
        yp[0] = make_float4(res[0], res[1], res[2], res[3]);
        yp[1] = make_float4(res[4], res[5], res[6], res[7]);
    }
}

// ---------------- final: out = relu(agg2 * norm_in + b2) ----------------
__global__ void k_out(const float* __restrict__ b2, float* __restrict__ out) {
    int i = blockIdx.x * blockDim.x + threadIdx.x;   // over N*F_OUT/4
    if (i >= N_NODES * F_OUT / 4) return;
    int n  = i / (F_OUT / 4);
    int cq = i - n * (F_OUT / 4);
    float ni = g_norm_in[n];
    float4 a = ((const float4*)g_agg)[i];
    float4 b = ((const float4*)b2)[cq];
    float4 o;
    o.x = fmaxf(a.x * ni + b.x, 0.f);
    o.y = fmaxf(a.y * ni + b.y, 0.f);
    o.z = fmaxf(a.z * ni + b.z, 0.f);
    o.w = fmaxf(a.w * ni + b.w, 0.f);
    ((float4*)out)[i] = o;
}

// ---------------- launch ----------------
extern "C" void kernel_launch(void* const* d_in, const int* in_sizes, int n_in,
                              void* d_out, int out_size) {
    const float* h   = (const float*)d_in[0];
    const float* W1  = (const float*)d_in[1];
    const float* b1  = (const float*)d_in[2];
    const float* W2  = (const float*)d_in[3];
    const float* b2  = (const float*)d_in[4];
    const int*   src = (const int*)d_in[5];   // JAX default x64-disabled: int32
    const int*   dst = (const int*)d_in[6];
    float*       out = (float*)d_out;

    float *agg, *h1, *y2;
    cudaGetSymbolAddress((void**)&agg, g_agg);
    cudaGetSymbolAddress((void**)&h1,  g_h1);
    cudaGetSymbolAddress((void**)&y2,  g_y2);

    const int SMEM1 = (128 * 128 + 128 * 132) * 4;   // 133120 B
    const int SMEM2 = (128 * 64  + 128 * 132) * 4;   // 100352 B
    cudaFuncSetAttribute((const void*)k_gemm<128, true>,
                         cudaFuncAttributeMaxDynamicSharedMemorySize, SMEM1);
    cudaFuncSetAttribute((const void*)k_gemm<64, false>,
                         cudaFuncAttributeMaxDynamicSharedMemorySize, SMEM2);

    const int T = 256;

    // norms
    k_zero_deg<<<(N_NODES + T - 1) / T, T>>>();
    k_deg<<<(N_EDGES + T - 1) / T, T>>>(src, dst);
    k_norm<<<(N_NODES + T - 1) / T, T>>>();

    // layer 1: agg = sum_e (h*norm_out)[src] -> dst; h1 = relu((agg*norm_in)@W1+b1)*norm_out
    k_zero_f4<<<(N_NODES * F_IN / 4 + T - 1) / T, T>>>((float4*)agg, N_NODES * F_IN / 4);
    k_scatter<32, true><<<(N_EDGES * 32 + T - 1) / T, T>>>(h, src, dst, agg);
    k_gemm<128, true><<<(N_NODES + 127) / 128, T, SMEM1>>>(agg, W1, b1, h1);

    // layer 2 (GEMM-before-aggregate): y2 = h1 @ W2; agg2 = sum_e y2[src] -> dst
    k_gemm<64, false><<<(N_NODES + 127) / 128, T, SMEM2>>>(h1, W2, nullptr, y2);
    k_zero_f4<<<(N_NODES * F_OUT / 4 + T - 1) / T, T>>>((float4*)agg, N_NODES * F_OUT / 4);
    k_scatter<16, false><<<(N_EDGES * 16 + T - 1) / T, T>>>(y2, src, dst, agg);

    // out = relu(agg2 * norm_in + b2)
    k_out<<<(N_NODES * F_OUT / 4 + T - 1) / T, T>>>(b2, out);
}

// round 4
// speedup vs baseline: 1.4202x; 1.4202x over previous
#include <cuda_runtime.h>
#include <cstdint>

#define N_NODES 50000
#define N_EDGES 800000
#define F_IN    128
#define F_HID   128
#define F_OUT   64
#define SCAN_B  1024
#define SCAN_NB ((N_NODES + SCAN_B - 1) / SCAN_B)   // 49

// ---------------- scratch (static device globals) ----------------
__device__ __align__(16) float g_agg[N_NODES * F_IN];   // layer1 aggregate [N,128]
__device__ __align__(16) float g_h1 [N_NODES * F_HID];  // relu(layer1)*norm_out [N,128]
__device__ __align__(16) float g_y2 [N_NODES * F_OUT];  // h1 @ W2 [N,64]
__device__ __align__(16) float g_norm_out[N_NODES];
__device__ __align__(16) float g_norm_in [N_NODES];
__device__ __align__(16) int   g_deg_out[N_NODES];
__device__ __align__(16) int   g_deg_in [N_NODES];
__device__ __align__(16) int   g_row_start[N_NODES];    // exclusive scan of deg_in
__device__ __align__(16) int   g_cursor[N_NODES];       // fill cursors
__device__ __align__(16) int   g_bsum[SCAN_NB];
__device__ __align__(16) int   g_csr_src[N_EDGES];      // src node id per CSR slot (grouped by dst)

__device__ __forceinline__ int clampi(int v) {
    return v < 0 ? 0 : (v >= N_NODES ? N_NODES - 1 : v);
}

__device__ __forceinline__ uint64_t fma2(uint64_t a, uint64_t b, uint64_t c) {
    uint64_t d;
    asm("fma.rn.f32x2 %0, %1, %2, %3;" : "=l"(d) : "l"(a), "l"(b), "l"(c));
    return d;
}

// ---------------- degrees + norms ----------------
__global__ void k_zero_deg() {
    int i = blockIdx.x * blockDim.x + threadIdx.x;
    if (i < N_NODES) { g_deg_out[i] = 0; g_deg_in[i] = 0; }
}

__global__ void k_deg(const int* __restrict__ src, const int* __restrict__ dst) {
    int e = blockIdx.x * blockDim.x + threadIdx.x;
    if (e < N_EDGES) {
        atomicAdd(&g_deg_out[clampi(src[e])], 1);
        atomicAdd(&g_deg_in [clampi(dst[e])], 1);
    }
}

__global__ void k_norm() {
    int i = blockIdx.x * blockDim.x + threadIdx.x;
    if (i < N_NODES) {
        g_norm_out[i] = rsqrtf((float)max(g_deg_out[i], 1));
        g_norm_in [i] = rsqrtf((float)max(g_deg_in [i], 1));
    }
}

// ---------------- CSR build: exclusive scan of deg_in + atomic fill ----------------
__global__ void k_scan1() {
    __shared__ int sh[SCAN_B];
    int i = blockIdx.x * SCAN_B + threadIdx.x;
    int v = (i < N_NODES) ? g_deg_in[i] : 0;
    sh[threadIdx.x] = v;
    __syncthreads();
#pragma unroll
    for (int off = 1; off < SCAN_B; off <<= 1) {
        int t = (threadIdx.x >= off) ? sh[threadIdx.x - off] : 0;
        __syncthreads();
        sh[threadIdx.x] += t;
        __syncthreads();
    }
    if (i < N_NODES) g_row_start[i] = sh[threadIdx.x] - v;   // exclusive
    if (threadIdx.x == SCAN_B - 1) g_bsum[blockIdx.x] = sh[threadIdx.x];
}

__global__ void k_scan2() {   // tiny: 49 partial sums, single thread
    if (threadIdx.x == 0) {
        int run = 0;
        for (int i = 0; i < SCAN_NB; i++) { int t = g_bsum[i]; g_bsum[i] = run; run += t; }
    }
}

__global__ void k_scan3() {
    int i = blockIdx.x * SCAN_B + threadIdx.x;
    if (i < N_NODES) {
        int rs = g_row_start[i] + g_bsum[blockIdx.x];
        g_row_start[i] = rs;
        g_cursor[i]    = rs;
    }
}

__global__ void k_fill(const int* __restrict__ src, const int* __restrict__ dst) {
    int e = blockIdx.x * blockDim.x + threadIdx.x;
    if (e < N_EDGES) {
        int d = clampi(dst[e]);
        int pos = atomicAdd(&g_cursor[d], 1);
        g_csr_src[pos] = clampi(src[e]);
    }
}

// ---------------- gather1: agg[n] = sum_{e: dst=n} h[src]*norm_out[src] ----------------
// one warp per node; lane owns float4 chunk q=lane (F_IN/4 = 32)
__global__ void k_gather1(const float* __restrict__ X) {
    int warp = (blockIdx.x * blockDim.x + threadIdx.x) >> 5;
    int lane = threadIdx.x & 31;
    if (warp >= N_NODES) return;
    int start = g_row_start[warp];
    int end   = start + g_deg_in[warp];
    const float4* X4 = (const float4*)X;
    float4 acc = make_float4(0.f, 0.f, 0.f, 0.f);
#pragma unroll 4
    for (int p = start; p < end; p++) {
        int s = __ldg(&g_csr_src[p]);                 // broadcast across warp
        float no = __ldg(&g_norm_out[s]);
        float4 v = __ldg(&X4[(size_t)s * 32 + lane]);
        acc.x = fmaf(v.x, no, acc.x);
        acc.y = fmaf(v.y, no, acc.y);
        acc.z = fmaf(v.z, no, acc.z);
        acc.w = fmaf(v.w, no, acc.w);
    }
    ((float4*)g_agg)[(size_t)warp * 32 + lane] = acc;
}

// ---------------- gather2 + output epilogue ----------------
// one warp per node; lane = (half, q) with q in [0,16): half-warps split edges, reduce at end.
__global__ void k_gather2(const float* __restrict__ b2, float* __restrict__ out) {
    int warp = (blockIdx.x * blockDim.x + threadIdx.x) >> 5;
    int lane = threadIdx.x & 31;
    if (warp >= N_NODES) return;
    int half = lane >> 4;
    int q    = lane & 15;
    int start = g_row_start[warp];
    int end   = start + g_deg_in[warp];
    const float4* Y4 = (const float4*)g_y2;
    float4 acc = make_float4(0.f, 0.f, 0.f, 0.f);
#pragma unroll 4
    for (int p = start + half; p < end; p += 2) {
        int s = __ldg(&g_csr_src[p]);
        float4 v = __ldg(&Y4[(size_t)s * 16 + q]);
        acc.x += v.x; acc.y += v.y; acc.z += v.z; acc.w += v.w;
    }
    acc.x += __shfl_xor_sync(0xffffffffu, acc.x, 16);
    acc.y += __shfl_xor_sync(0xffffffffu, acc.y, 16);
    acc.z += __shfl_xor_sync(0xffffffffu, acc.z, 16);
    acc.w += __shfl_xor_sync(0xffffffffu, acc.w, 16);
    if (half == 0) {
        float ni = g_norm_in[warp];
        float4 b = ((const float4*)b2)[q];
        float4 o;
        o.x = fmaxf(fmaf(acc.x, ni, b.x), 0.f);
        o.y = fmaxf(fmaf(acc.y, ni, b.y), 0.f);
        o.z = fmaxf(fmaf(acc.z, ni, b.z), 0.f);
        o.w = fmaxf(fmaf(acc.w, ni, b.w), 0.f);
        ((float4*)out)[(size_t)warp * 16 + q] = o;
    }
}

// ---------------- tiled fp32 GEMM with packed f32x2 FMA ----------------
// K = 128 fixed. Tile: 128 rows x NCOLS cols, 256 threads.
// LAYER1: scale rows by norm_in on load; epilogue = relu(+bias)*norm_out.
template<int NCOLS, bool LAYER1>
__global__ void k_gemm(const float* __restrict__ X, const float* __restrict__ W,
                       const float* __restrict__ bias, float* __restrict__ Y) {
    constexpr int K   = 128;
    constexpr int TM  = 128;
    constexpr int CG  = NCOLS / 8;     // column groups (8 cols each)
    constexpr int RG  = 256 / CG;      // row groups
    constexpr int RPT = TM / RG;       // rows per thread
    constexpr int XLD = 132;           // padded X row stride (floats)

    extern __shared__ float sm[];
    float* sW = sm;                    // [K][NCOLS]
    float* sX = sm + K * NCOLS;        // [TM][XLD]

    int t    = threadIdx.x;
    int row0 = blockIdx.x * TM;

    for (int i = t; i < K * NCOLS / 4; i += 256)
        ((float4*)sW)[i] = ((const float4*)W)[i];

    {
        int kq = t & 31;
        int rr = t >> 5;
        for (int r = rr; r < TM; r += 8) {
            int gr = row0 + r;
            float4 v = make_float4(0.f, 0.f, 0.f, 0.f);
            if (gr < N_NODES) {
                v = ((const float4*)X)[(size_t)gr * (K / 4) + kq];
                if (LAYER1) {
                    float s = g_norm_in[gr];
                    v.x *= s; v.y *= s; v.z *= s; v.w *= s;
                }
            }
            *(float4*)(sX + r * XLD + kq * 4) = v;
        }
    }
    __syncthreads();

    int cg = t % CG;
    int rg = t / CG;
    int c0 = cg * 8;

    uint64_t acc2[RPT][4];
#pragma unroll
    for (int i = 0; i < RPT; i++)
#pragma unroll
        for (int p = 0; p < 4; p++) acc2[i][p] = 0ull;

#pragma unroll 2
    for (int k4 = 0; k4 < K / 4; k4++) {
        float4 xv[RPT];
#pragma unroll
        for (int i = 0; i < RPT; i++)
            xv[i] = *(const float4*)(sX + (rg * RPT + i) * XLD + k4 * 4);
#pragma unroll
        for (int kk = 0; kk < 4; kk++) {
            int k = k4 * 4 + kk;
            ulonglong2 wa = *(const ulonglong2*)(sW + k * NCOLS + c0);
            ulonglong2 wb = *(const ulonglong2*)(sW + k * NCOLS + c0 + 4);
#pragma unroll
            for (int i = 0; i < RPT; i++) {
                float x = (&xv[i].x)[kk];
                uint64_t xx;
                asm("mov.b64 %0, {%1, %1};" : "=l"(xx) : "f"(x));
                acc2[i][0] = fma2(xx, wa.x, acc2[i][0]);
                acc2[i][1] = fma2(xx, wa.y, acc2[i][1]);
                acc2[i][2] = fma2(xx, wb.x, acc2[i][2]);
                acc2[i][3] = fma2(xx, wb.y, acc2[i][3]);
            }
        }
    }

#pragma unroll
    for (int i = 0; i < RPT; i++) {
        int gr = row0 + rg * RPT + i;
        if (gr >= N_NODES) continue;
        float so = LAYER1 ? g_norm_out[gr] : 1.f;
        float res[8];
#pragma unroll
        for (int p = 0; p < 4; p++) {
            float lo, hi;
            asm("mov.b64 {%0, %1}, %2;" : "=f"(lo), "=f"(hi) : "l"(acc2[i][p]));
            res[2 * p]     = lo;
            res[2 * p + 1] = hi;
        }
        if (LAYER1) {
#pragma unroll
            for (int j = 0; j < 8; j++) {
                float v = res[j] + bias[c0 + j];
                res[j] = fmaxf(v, 0.f) * so;   // relu(z)*s == relu(z*s), s>0
            }
        }
        float4* yp = (float4*)(Y + (size_t)gr * NCOLS + c0);
        yp[0] = make_float4(res[0], res[1], res[2], res[3]);
        yp[1] = make_float4(res[4], res[5], res[6], res[7]);
    }
}

// ---------------- launch ----------------
extern "C" void kernel_launch(void* const* d_in, const int* in_sizes, int n_in,
                              void* d_out, int out_size) {
    const float* h   = (const float*)d_in[0];
    const float* W1  = (const float*)d_in[1];
    const float* b1  = (const float*)d_in[2];
    const float* W2  = (const float*)d_in[3];
    const float* b2  = (const float*)d_in[4];
    const int*   src = (const int*)d_in[5];   // JAX x64-disabled: int32
    const int*   dst = (const int*)d_in[6];
    float*       out = (float*)d_out;

    float *agg, *h1, *y2;
    cudaGetSymbolAddress((void**)&agg, g_agg);
    cudaGetSymbolAddress((void**)&h1,  g_h1);
    cudaGetSymbolAddress((void**)&y2,  g_y2);

    const int SMEM1 = (128 * 128 + 128 * 132) * 4;   // 133120 B
    const int SMEM2 = (128 * 64  + 128 * 132) * 4;   // 100352 B
    cudaFuncSetAttribute((const void*)k_gemm<128, true>,
                         cudaFuncAttributeMaxDynamicSharedMemorySize, SMEM1);
    cudaFuncSetAttribute((const void*)k_gemm<64, false>,
                         cudaFuncAttributeMaxDynamicSharedMemorySize, SMEM2);

    const int T = 256;

    // degrees, norms, CSR
    k_zero_deg<<<(N_NODES + T - 1) / T, T>>>();
    k_deg<<<(N_EDGES + T - 1) / T, T>>>(src, dst);
    k_norm<<<(N_NODES + T - 1) / T, T>>>();
    k_scan1<<<SCAN_NB, SCAN_B>>>();
    k_scan2<<<1, 32>>>();
    k_scan3<<<SCAN_NB, SCAN_B>>>();
    k_fill<<<(N_EDGES + T - 1) / T, T>>>(src, dst);

    // layer 1: gather (scaled) -> GEMM1 (norm_in on load, relu+bias+norm_out epilogue)
    k_gather1<<<(N_NODES * 32 + T - 1) / T, T>>>(h);
    k_gemm<128, true><<<(N_NODES + 127) / 128, T, SMEM1>>>(agg, W1, b1, h1);

    // layer 2: GEMM-before-aggregate, then fused gather + relu(.*norm_in + b2) -> out
    k_gemm<64, false><<<(N_NODES + 127) / 128, T, SMEM2>>>(h1, W2, nullptr, y2);
    k_gather2<<<(N_NODES * 32 + T - 1) / T, T>>>(b2, out);
}

// round 5
// speedup vs baseline: 1.4430x; 1.0160x over previous
#include <cuda_runtime.h>
#include <cuda_fp16.h>
#include <cstdint>

#define N_NODES 50000
#define N_EDGES 800000
#define F_IN    128
#define F_HID   128
#define F_OUT   64
#define SCAN_B  1024
#define SCAN_NB ((N_NODES + SCAN_B - 1) / SCAN_B)   // 49

// ---------------- scratch (static device globals) ----------------
__device__ __align__(16) float  g_agg[N_NODES * F_IN];   // layer1 aggregate [N,128] fp32
__device__ __align__(16) float  g_h1 [N_NODES * F_HID];  // relu(layer1)*norm_out [N,128] fp32
__device__ __align__(16) __half g_xh [N_NODES * F_IN];   // (h * norm_out) as fp16 [N,128]
__device__ __align__(16) __half g_y2h[N_NODES * F_OUT];  // h1 @ W2 as fp16 [N,64]
__device__ __align__(16) float  g_norm_out[N_NODES];
__device__ __align__(16) float  g_norm_in [N_NODES];
__device__ __align__(16) int    g_deg_out[N_NODES];
__device__ __align__(16) int    g_deg_in [N_NODES];
__device__ __align__(16) int    g_row_start[N_NODES];    // exclusive scan of deg_in
__device__ __align__(16) int    g_cursor[N_NODES];
__device__ __align__(16) int    g_bsum[64];
__device__ __align__(16) int    g_csr_src[N_EDGES];      // src id per CSR slot (grouped by dst)

__device__ __forceinline__ int clampi(int v) {
    return v < 0 ? 0 : (v >= N_NODES ? N_NODES - 1 : v);
}

__device__ __forceinline__ uint64_t fma2(uint64_t a, uint64_t b, uint64_t c) {
    uint64_t d;
    asm("fma.rn.f32x2 %0, %1, %2, %3;" : "=l"(d) : "l"(a), "l"(b), "l"(c));
    return d;
}

// ---------------- degrees ----------------
__global__ void k_deg(const int* __restrict__ src, const int* __restrict__ dst) {
    int e = blockIdx.x * blockDim.x + threadIdx.x;
    if (e < N_EDGES) {
        atomicAdd(&g_deg_out[clampi(src[e])], 1);
        atomicAdd(&g_deg_in [clampi(dst[e])], 1);
    }
}

// ---------------- scan (warp-shuffle) ----------------
__global__ void k_scan1() {
    __shared__ int wt[32];
    int i    = blockIdx.x * SCAN_B + threadIdx.x;
    int lane = threadIdx.x & 31;
    int wid  = threadIdx.x >> 5;
    int v = (i < N_NODES) ? g_deg_in[i] : 0;
    int x = v;
#pragma unroll
    for (int off = 1; off < 32; off <<= 1) {
        int t = __shfl_up_sync(0xffffffffu, x, off);
        if (lane >= off) x += t;
    }
    if (lane == 31) wt[wid] = x;
    __syncthreads();
    if (wid == 0) {
        int y = wt[lane];
#pragma unroll
        for (int off = 1; off < 32; off <<= 1) {
            int t = __shfl_up_sync(0xffffffffu, y, off);
            if (lane >= off) y += t;
        }
        wt[lane] = y;
    }
    __syncthreads();
    if (wid > 0) x += wt[wid - 1];
    if (i < N_NODES) g_row_start[i] = x - v;            // exclusive within block
    if (threadIdx.x == SCAN_B - 1) g_bsum[blockIdx.x] = x;
}

__global__ void k_scan2() {   // 64 threads: scan SCAN_NB block totals
    __shared__ int w0;
    int i = threadIdx.x;
    int lane = i & 31;
    int v = (i < SCAN_NB) ? g_bsum[i] : 0;
    int x = v;
#pragma unroll
    for (int off = 1; off < 32; off <<= 1) {
        int t = __shfl_up_sync(0xffffffffu, x, off);
        if (lane >= off) x += t;
    }
    if (i == 31) w0 = x;
    __syncthreads();
    if (i >= 32) x += w0;
    if (i < SCAN_NB) g_bsum[i] = x - v;                 // exclusive
}

// add block offsets + init cursor + compute norms (fused)
__global__ void k_scan3() {
    int i = blockIdx.x * SCAN_B + threadIdx.x;
    if (i < N_NODES) {
        int rs = g_row_start[i] + g_bsum[blockIdx.x];
        g_row_start[i] = rs;
        g_cursor[i]    = rs;
        g_norm_out[i]  = rsqrtf((float)max(g_deg_out[i], 1));
        g_norm_in [i]  = rsqrtf((float)max(g_deg_in [i], 1));
    }
}

__global__ void k_fill(const int* __restrict__ src, const int* __restrict__ dst) {
    int e = blockIdx.x * blockDim.x + threadIdx.x;
    if (e < N_EDGES) {
        int d = clampi(dst[e]);
        int pos = atomicAdd(&g_cursor[d], 1);
        g_csr_src[pos] = clampi(src[e]);
    }
}

// ---------------- convert: xh[n] = fp16(h[n] * norm_out[n]) ----------------
// one thread per 8 features
__global__ void k_conv(const float* __restrict__ X) {
    int idx = blockIdx.x * blockDim.x + threadIdx.x;   // over N*16
    if (idx >= N_NODES * 16) return;
    int n = idx >> 4;
    float no = g_norm_out[n];
    float4 a = ((const float4*)X)[idx * 2];
    float4 b = ((const float4*)X)[idx * 2 + 1];
    __half2 h0 = __floats2half2_rn(a.x * no, a.y * no);
    __half2 h1 = __floats2half2_rn(a.z * no, a.w * no);
    __half2 h2 = __floats2half2_rn(b.x * no, b.y * no);
    __half2 h3 = __floats2half2_rn(b.z * no, b.w * no);
    uint4 u;
    u.x = *(uint32_t*)&h0; u.y = *(uint32_t*)&h1;
    u.z = *(uint32_t*)&h2; u.w = *(uint32_t*)&h3;
    ((uint4*)g_xh)[idx] = u;
}

// ---------------- gather1: agg[n] = sum_{e: dst=n} xh[src]  (fp32 accum) ----------------
// one warp per node; lane owns 4 features (uint2 = 2 half2)
__global__ void k_gather1() {
    int warp = (blockIdx.x * blockDim.x + threadIdx.x) >> 5;
    int lane = threadIdx.x & 31;
    if (warp >= N_NODES) return;
    int start = g_row_start[warp];
    int end   = start + g_deg_in[warp];
    const uint2* X2 = (const uint2*)g_xh;
    float4 acc = make_float4(0.f, 0.f, 0.f, 0.f);
#pragma unroll 4
    for (int p = start; p < end; p++) {
        int s = __ldg(&g_csr_src[p]);
        uint2 v = __ldg(&X2[(size_t)s * 32 + lane]);
        float2 f0 = __half22float2(*(__half2*)&v.x);
        float2 f1 = __half22float2(*(__half2*)&v.y);
        acc.x += f0.x; acc.y += f0.y; acc.z += f1.x; acc.w += f1.y;
    }
    ((float4*)g_agg)[(size_t)warp * 32 + lane] = acc;
}

// ---------------- gather2 + output epilogue ----------------
// one warp per node; lane owns feature pair (half2); out = relu(acc*norm_in + b2)
__global__ void k_gather2(const float* __restrict__ b2, float* __restrict__ out) {
    int warp = (blockIdx.x * blockDim.x + threadIdx.x) >> 5;
    int lane = threadIdx.x & 31;
    if (warp >= N_NODES) return;
    int start = g_row_start[warp];
    int end   = start + g_deg_in[warp];
    const uint32_t* Y1 = (const uint32_t*)g_y2h;
    float2 acc = make_float2(0.f, 0.f);
#pragma unroll 4
    for (int p = start; p < end; p++) {
        int s = __ldg(&g_csr_src[p]);
        uint32_t v = __ldg(&Y1[(size_t)s * 32 + lane]);
        float2 f = __half22float2(*(__half2*)&v);
        acc.x += f.x; acc.y += f.y;
    }
    float ni = g_norm_in[warp];
    float2 b = ((const float2*)b2)[lane];
    float2 o;
    o.x = fmaxf(fmaf(acc.x, ni, b.x), 0.f);
    o.y = fmaxf(fmaf(acc.y, ni, b.y), 0.f);
    ((float2*)out)[(size_t)warp * 32 + lane] = o;
}

// ---------------- tiled fp32 GEMM with packed f32x2 FMA ----------------
// K = 128 fixed. Tile: 128 rows x NCOLS cols, 256 threads.
// LAYER1: scale rows by norm_in on load; epilogue relu(+bias)*norm_out -> fp32 Y.
// HALF_OUT: write fp16 to Yh (no bias/relu).
template<int NCOLS, bool LAYER1, bool HALF_OUT>
__global__ void k_gemm(const float* __restrict__ X, const float* __restrict__ W,
                       const float* __restrict__ bias, float* __restrict__ Y,
                       __half* __restrict__ Yh) {
    constexpr int K   = 128;
    constexpr int TM  = 128;
    constexpr int CG  = NCOLS / 8;
    constexpr int RG  = 256 / CG;
    constexpr int RPT = TM / RG;
    constexpr int XLD = 132;

    extern __shared__ float sm[];
    float* sW = sm;                    // [K][NCOLS]
    float* sX = sm + K * NCOLS;        // [TM][XLD]

    int t    = threadIdx.x;
    int row0 = blockIdx.x * TM;

    for (int i = t; i < K * NCOLS / 4; i += 256)
        ((float4*)sW)[i] = ((const float4*)W)[i];

    {
        int kq = t & 31;
        int rr = t >> 5;
        for (int r = rr; r < TM; r += 8) {
            int gr = row0 + r;
            float4 v = make_float4(0.f, 0.f, 0.f, 0.f);
            if (gr < N_NODES) {
                v = ((const float4*)X)[(size_t)gr * (K / 4) + kq];
                if (LAYER1) {
                    float s = g_norm_in[gr];
                    v.x *= s; v.y *= s; v.z *= s; v.w *= s;
                }
            }
            *(float4*)(sX + r * XLD + kq * 4) = v;
        }
    }
    __syncthreads();

    int cg = t % CG;
    int rg = t / CG;
    int c0 = cg * 8;

    uint64_t acc2[RPT][4];
#pragma unroll
    for (int i = 0; i < RPT; i++)
#pragma unroll
        for (int p = 0; p < 4; p++) acc2[i][p] = 0ull;

#pragma unroll 2
    for (int k4 = 0; k4 < K / 4; k4++) {
        float4 xv[RPT];
#pragma unroll
        for (int i = 0; i < RPT; i++)
            xv[i] = *(const float4*)(sX + (rg * RPT + i) * XLD + k4 * 4);
#pragma unroll
        for (int kk = 0; kk < 4; kk++) {
            int k = k4 * 4 + kk;
            ulonglong2 wa = *(const ulonglong2*)(sW + k * NCOLS + c0);
            ulonglong2 wb = *(const ulonglong2*)(sW + k * NCOLS + c0 + 4);
#pragma unroll
            for (int i = 0; i < RPT; i++) {
                float x = (&xv[i].x)[kk];
                uint64_t xx;
                asm("mov.b64 %0, {%1, %1};" : "=l"(xx) : "f"(x));
                acc2[i][0] = fma2(xx, wa.x, acc2[i][0]);
                acc2[i][1] = fma2(xx, wa.y, acc2[i][1]);
                acc2[i][2] = fma2(xx, wb.x, acc2[i][2]);
                acc2[i][3] = fma2(xx, wb.y, acc2[i][3]);
            }
        }
    }

#pragma unroll
    for (int i = 0; i < RPT; i++) {
        int gr = row0 + rg * RPT + i;
        if (gr >= N_NODES) continue;
        float res[8];
#pragma unroll
        for (int p = 0; p < 4; p++) {
            float lo, hi;
            asm("mov.b64 {%0, %1}, %2;" : "=f"(lo), "=f"(hi) : "l"(acc2[i][p]));
            res[2 * p]     = lo;
            res[2 * p + 1] = hi;
        }
        if (LAYER1) {
            float so = g_norm_out[gr];
#pragma unroll
            for (int j = 0; j < 8; j++) {
                float v = res[j] + bias[c0 + j];
                res[j] = fmaxf(v, 0.f) * so;   // relu(z)*s == relu(z*s), s>0
            }
        }
        if (HALF_OUT) {
            __half2 p0 = __floats2half2_rn(res[0], res[1]);
            __half2 p1 = __floats2half2_rn(res[2], res[3]);
            __half2 p2 = __floats2half2_rn(res[4], res[5]);
            __half2 p3 = __floats2half2_rn(res[6], res[7]);
            uint4 u;
            u.x = *(uint32_t*)&p0; u.y = *(uint32_t*)&p1;
            u.z = *(uint32_t*)&p2; u.w = *(uint32_t*)&p3;
            *(uint4*)(Yh + (size_t)gr * NCOLS + c0) = u;
        } else {
            float4* yp = (float4*)(Y + (size_t)gr * NCOLS + c0);
            yp[0] = make_float4(res[0], res[1], res[2], res[3]);
            yp[1] = make_float4(res[4], res[5], res[6], res[7]);
        }
    }
}

// ---------------- launch ----------------
extern "C" void kernel_launch(void* const* d_in, const int* in_sizes, int n_in,
                              void* d_out, int out_size) {
    const float* h   = (const float*)d_in[0];
    const float* W1  = (const float*)d_in[1];
    const float* b1  = (const float*)d_in[2];
    const float* W2  = (const float*)d_in[3];
    const float* b2  = (const float*)d_in[4];
    const int*   src = (const int*)d_in[5];   // JAX x64-disabled: int32
    const int*   dst = (const int*)d_in[6];
    float*       out = (float*)d_out;

    float *agg, *h1;
    __half* y2h;
    int *dego, *degi;
    cudaGetSymbolAddress((void**)&agg,  g_agg);
    cudaGetSymbolAddress((void**)&h1,   g_h1);
    cudaGetSymbolAddress((void**)&y2h,  g_y2h);
    cudaGetSymbolAddress((void**)&dego, g_deg_out);
    cudaGetSymbolAddress((void**)&degi, g_deg_in);

    const int SMEM1 = (128 * 128 + 128 * 132) * 4;   // 133120 B
    const int SMEM2 = (128 * 64  + 128 * 132) * 4;   // 100352 B
    cudaFuncSetAttribute((const void*)k_gemm<128, true,  false>,
                         cudaFuncAttributeMaxDynamicSharedMemorySize, SMEM1);
    cudaFuncSetAttribute((const void*)k_gemm<64,  false, true>,
                         cudaFuncAttributeMaxDynamicSharedMemorySize, SMEM2);

    const int T = 256;

    // degrees, norms, CSR
    cudaMemsetAsync(dego, 0, N_NODES * sizeof(int));
    cudaMemsetAsync(degi, 0, N_NODES * sizeof(int));
    k_deg<<<(N_EDGES + T - 1) / T, T>>>(src, dst);
    k_scan1<<<SCAN_NB, SCAN_B>>>();
    k_scan2<<<1, 64>>>();
    k_scan3<<<SCAN_NB, SCAN_B>>>();
    k_fill<<<(N_EDGES + T - 1) / T, T>>>(src, dst);

    // fp16 pre-scaled features
    k_conv<<<(N_NODES * 16 + T - 1) / T, T>>>(h);

    // layer 1: gather fp16 -> GEMM1 (norm_in on load, relu+bias+norm_out epilogue)
    k_gather1<<<(N_NODES * 32 + T - 1) / T, T>>>();
    k_gemm<128, true, false><<<(N_NODES + 127) / 128, T, SMEM1>>>(agg, W1, b1, h1, nullptr);

    // layer 2: GEMM (fp16 out) -> fused gather + relu(.*norm_in + b2) -> out
    k_gemm<64, false, true><<<(N_NODES + 127) / 128, T, SMEM2>>>(h1, W2, nullptr, nullptr, y2h);
    k_gather2<<<(N_NODES * 32 + T - 1) / T, T>>>(b2, out);
}